// round 17
// baseline (speedup 1.0000x reference)
#include <cuda_runtime.h>

#define B  32
#define L  1024
#define D  512
#define NN 512

// 32 partial-sum planes of sum_l(i - j) over L-chunks of 32: [32][B][D]
__device__ float g_part[32 * B * D];
// DCE-defeating sink for the W prefetch
__device__ float g_sink;

// ---------------------------------------------------------------------------
// Kernel 1 (NEW layout): part[ch][b][d] = sum_{l in 32-row chunk ch}(i - j)
// Grid: B(32) * 32 L-chunks = 1024 blocks x 256 thr, all resident
// (<=32 regs, 8 blocks/SM). Thread map: dq = tid&127 covers a FULL 2KB row
// (128 float4 = 512 floats = D) -> each thread's d is FIXED; lg = tid>>7
// (2 row-groups x 16 rows). Each block streams a fully CONTIGUOUS 64KB
// region (i) + 64KB (j) in sequential row order — ideal DRAM pattern.
// Final reduce: one pairwise add (tid vs tid+128), then 128 float4 stores.
// __ldcs streaming so W stays in L2. Side job: prefetch W (1 MB) into L2.
// ---------------------------------------------------------------------------
__global__ void __launch_bounds__(256, 8) mean_diff_kernel(
    const float* __restrict__ gi, const float* __restrict__ gj,
    const float* __restrict__ W)
{
    const int blk = blockIdx.x;
    const int b   = blk >> 5;         // batch
    const int ch  = blk & 31;         // 32-row L-chunk
    const int tid = threadIdx.x;
    const int dq  = tid & 127;        // float4 col: full row coverage
    const int lg  = tid >> 7;         // row-group 0..1 (16 rows each)

    // --- W prefetch: 1024 blocks x 64 float4 = 1 MB into L2 ---
    if (tid < 64) {
        float4 w = __ldcg(((const float4*)W) + blk * 64 + tid);
        float t = w.x + w.y + w.z + w.w;
        if (__float_as_int(t) == 0x7f800001)  // never true in practice
            g_sink = t;
    }

    const int rowq = D / 4;           // 128 float4 per row
    const int l0   = ch * 32 + lg * 16;
    const float4* pi = (const float4*)(gi + (size_t)b * L * D) + (size_t)l0 * rowq + dq;
    const float4* pj = (const float4*)(gj + (size_t)b * L * D) + (size_t)l0 * rowq + dq;

    float4 acc = make_float4(0.f, 0.f, 0.f, 0.f);
    #pragma unroll
    for (int rr = 0; rr < 16; rr++) {
        float4 a = __ldcs(pi + (size_t)rr * rowq);
        float4 c = __ldcs(pj + (size_t)rr * rowq);
        acc.x += a.x - c.x;
        acc.y += a.y - c.y;
        acc.z += a.z - c.z;
        acc.w += a.w - c.w;
    }

    __shared__ float4 s[256];
    s[tid] = acc;
    __syncthreads();

    // single pairwise reduce: row-group 0 + row-group 1 (same d)
    if (tid < 128) {
        float4 o = s[tid + 128];
        float4 r = s[tid];
        r.x += o.x; r.y += o.y; r.z += o.z; r.w += o.w;
        ((float4*)(g_part + ch * B * D + b * D))[tid] = r;
    }
}

// ---------------------------------------------------------------------------
// Kernel 2 (R6's proven 6.27us structure; prologue now sums 32 planes):
// md[b,d] = (1/L) * sum_ch part[ch][b][d]
// u[b,n]  = sum_d md[b,d] * W[d,n]
// out[b,n] = 0.5*(relu(u + bias[n]) + relu(bias[n] - u))
// Grid: 16 batch-pairs * 16 n-tiles(32 wide) = 256 blocks x 512 threads.
// Per thread: 32 fully-unrolled independent W loads (L2-hot after prefetch),
// each reused for 2 batches.
// ---------------------------------------------------------------------------
__global__ void __launch_bounds__(512) gemv_combine_kernel(
    const float* __restrict__ W, const float* __restrict__ bias,
    float* __restrict__ out)
{
    const int blk  = blockIdx.x;
    const int bg   = blk >> 4;        // batch pair (2 batches)
    const int nt   = blk & 15;        // 32-wide n tile
    const int b0   = bg * 2;
    const int tid  = threadIdx.x;
    const int nloc = tid & 31;
    const int dg   = tid >> 5;        // d-group 0..15 (32 rows each)

    __shared__ float smd[2][D];
    {
        const float inv = 1.0f / (float)L;
        #pragma unroll
        for (int bb = 0; bb < 2; bb++) {
            const float* p = g_part + (b0 + bb) * D + tid;
            float v = 0.f;
            #pragma unroll
            for (int pl = 0; pl < 32; pl++)
                v += p[pl * B * D];
            smd[bb][tid] = v * inv;
        }
    }
    __syncthreads();

    const int n = nt * 32 + nloc;
    const float* Wp = W + (size_t)(dg * 32) * NN + n;

    float u0 = 0.f, u1 = 0.f;
    #pragma unroll
    for (int d = 0; d < 32; d++) {
        float w = __ldg(Wp + (size_t)d * NN);
        int di = dg * 32 + d;
        u0 = fmaf(smd[0][di], w, u0);
        u1 = fmaf(smd[1][di], w, u1);
    }

    __shared__ float su[2][512];
    su[0][tid] = u0;
    su[1][tid] = u1;
    __syncthreads();

    // 64 results (2 batches x 32 n), each a 16-way partial sum.
    if (tid < 64) {
        const int bb = tid >> 5;      // batch within pair
        const int nn = tid & 31;
        float t = 0.f;
        #pragma unroll
        for (int g = 0; g < 16; g++)
            t += su[bb][g * 32 + nn];
        float bv = bias[nt * 32 + nn];
        out[(b0 + bb) * NN + nt * 32 + nn] =
            0.5f * (fmaxf(t + bv, 0.f) + fmaxf(bv - t, 0.f));
    }
}

extern "C" void kernel_launch(void* const* d_in, const int* in_sizes, int n_in,
                              void* d_out, int out_size)
{
    const float* gi   = (const float*)d_in[0];   // i     [B, L, D]
    const float* gj   = (const float*)d_in[1];   // j     [B, L, D]
    const float* W    = (const float*)d_in[2];   // W_agg [D, NN]
    const float* bias = (const float*)d_in[3];   // b_agg [NN]
    float* out = (float*)d_out;                  // [B, NN]

    mean_diff_kernel<<<1024, 256>>>(gi, gj, W);
    gemv_combine_kernel<<<256, 512>>>(W, bias, out);
}